// round 7
// baseline (speedup 1.0000x reference)
#include <cuda_runtime.h>
#include <cstdint>

// ---------------- problem constants ----------------
#define B_    64
#define N_    482
#define DIM_  512
#define H_    8
#define D_    64
#define QKV_  1536
#define BH_   (B_*H_)          // 512
#define BN_   (B_*N_)          // 30848
#define SZ_BND (BN_*DIM_)      // 15794176
#define NHW_  256
#define NB_   225
#define TAIL0_ 257
#define SCALE_ 0.125f

// ---------------- device scratch ----------------
__device__ float g_qkv [(size_t)BN_*QKV_];
__device__ float g_qkvm[(size_t)BN_*QKV_];
__device__ float g_qq  [(size_t)BH_*N_*D_];
__device__ float g_kk  [(size_t)BH_*N_*D_];
__device__ float g_vv  [(size_t)BH_*N_*D_];
__device__ float g_vm  [(size_t)BH_*N_*D_];
__device__ float g_out [SZ_BND];
__device__ float g_m   [SZ_BND];
__device__ float g_out2[SZ_BND];
__device__ float g_m2  [SZ_BND];
__device__ float g_max [B_*H_*3*D_];
__device__ float g_upd [BN_];
__device__ float g_mm  [B_*(N_-1)];

// ---------------- tf32 mma helpers ----------------
__device__ __forceinline__ void mma_tf32(float* c, const uint32_t* a, const uint32_t* b) {
    asm volatile("mma.sync.aligned.m16n8k8.row.col.f32.tf32.tf32.f32 "
        "{%0,%1,%2,%3}, {%4,%5,%6,%7}, {%8,%9}, {%0,%1,%2,%3};"
        : "+f"(c[0]), "+f"(c[1]), "+f"(c[2]), "+f"(c[3])
        : "r"(a[0]), "r"(a[1]), "r"(a[2]), "r"(a[3]), "r"(b[0]), "r"(b[1]));
}
__device__ __forceinline__ uint32_t to_tf32(float x) {
    uint32_t h;
    asm("cvt.rna.tf32.f32 %0, %1;" : "=r"(h) : "f"(x));
    return h;
}
__device__ __forceinline__ uint4 to_tf32_v4(float4 v) {
    uint4 r;
    r.x = to_tf32(v.x); r.y = to_tf32(v.y); r.z = to_tf32(v.z); r.w = to_tf32(v.w);
    return r;
}

extern __shared__ uint32_t s_dyn[];

// ================= pipelined single-pass tf32 NT GEMM, 128x128 tile =================
// C[m,n] = sum_k A[m*lda+k] * f(B[n*ldb+k]) (+bias[n]); M,N multiples of 128, K of 32.
// Double-buffered smem, register-staged prefetch, ONE syncthreads per k-slab.
#define GEMM_BUF (128*36)
#define GEMM_SMEM_BYTES (4 * GEMM_BUF * 4 * 2 / 2)   // 2 bufs * 2 tensors * 128*36 * 4B = 73728
template<bool ABS_B, bool BIAS>
__global__ void __launch_bounds__(256) mma_gemm(const float* __restrict__ A,
                                                const float* __restrict__ Bm,
                                                const float* __restrict__ bias,
                                                float* __restrict__ C,
                                                int K, int lda, int ldb, int ldc)
{
    uint32_t* AsB = s_dyn;                 // [2][128][36]
    uint32_t* BsB = s_dyn + 2 * GEMM_BUF;  // [2][128][36]
    const int tid = threadIdx.x;
    const int bm = blockIdx.y * 128, bn = blockIdx.x * 128;
    const int lane = tid & 31, wid = tid >> 5;
    const int gr = lane >> 2, gc = lane & 3;
    const int wm = (wid & 1) * 64, wn = (wid >> 1) * 32;
    const int lr = tid >> 3, lc = (tid & 7) * 4;
    const float* Ap = A  + (size_t)(bm + lr) * lda + lc;
    const float* Bp = Bm + (size_t)(bn + lr) * ldb + lc;

    float acc[4][4][4];
    #pragma unroll
    for (int i = 0; i < 4; i++)
        #pragma unroll
        for (int j = 0; j < 4; j++)
            #pragma unroll
            for (int e = 0; e < 4; e++) acc[i][j][e] = 0.f;

    float4 avr[4], bvr[4];
    #pragma unroll
    for (int r = 0; r < 4; r++) {
        avr[r] = *(const float4*)(Ap + (size_t)(r * 32) * lda);
        bvr[r] = *(const float4*)(Bp + (size_t)(r * 32) * ldb);
    }

    const int nslab = K >> 5;
    for (int s = 0; s < nslab; s++) {
        uint32_t* As = AsB + (s & 1) * GEMM_BUF;
        uint32_t* Bs = BsB + (s & 1) * GEMM_BUF;
        #pragma unroll
        for (int r = 0; r < 4; r++) {
            float4 bv = bvr[r];
            if (ABS_B) { bv.x = fabsf(bv.x); bv.y = fabsf(bv.y); bv.z = fabsf(bv.z); bv.w = fabsf(bv.w); }
            *(uint4*)&As[(lr + r*32) * 36 + lc] = to_tf32_v4(avr[r]);
            *(uint4*)&Bs[(lr + r*32) * 36 + lc] = to_tf32_v4(bv);
        }
        if (s + 1 < nslab) {
            int kt = (s + 1) * 32;
            #pragma unroll
            for (int r = 0; r < 4; r++) {
                avr[r] = *(const float4*)(Ap + (size_t)(r * 32) * lda + kt);
                bvr[r] = *(const float4*)(Bp + (size_t)(r * 32) * ldb + kt);
            }
        }
        __syncthreads();
        #pragma unroll
        for (int ks = 0; ks < 4; ks++) {
            const int k0 = ks * 8;
            uint32_t ah[4][4], bh[4][2];
            #pragma unroll
            for (int mt = 0; mt < 4; mt++) {
                int r0 = wm + mt * 16 + gr;
                ah[mt][0] = As[(r0    ) * 36 + k0 + gc    ];
                ah[mt][1] = As[(r0 + 8) * 36 + k0 + gc    ];
                ah[mt][2] = As[(r0    ) * 36 + k0 + gc + 4];
                ah[mt][3] = As[(r0 + 8) * 36 + k0 + gc + 4];
            }
            #pragma unroll
            for (int nt = 0; nt < 4; nt++) {
                int c0 = wn + nt * 8 + gr;
                bh[nt][0] = Bs[c0 * 36 + k0 + gc    ];
                bh[nt][1] = Bs[c0 * 36 + k0 + gc + 4];
            }
            #pragma unroll
            for (int mt = 0; mt < 4; mt++)
                #pragma unroll
                for (int nt = 0; nt < 4; nt++)
                    mma_tf32(acc[mt][nt], ah[mt], bh[nt]);
        }
    }
    #pragma unroll
    for (int mt = 0; mt < 4; mt++)
        #pragma unroll
        for (int nt = 0; nt < 4; nt++) {
            int m0 = bm + wm + mt * 16 + gr;
            int n0 = bn + wn + nt * 8 + gc * 2;
            float bx = 0.f, by = 0.f;
            if (BIAS) { bx = bias[n0]; by = bias[n0 + 1]; }
            *(float2*)&C[(size_t)m0 * ldc + n0] = make_float2(acc[mt][nt][0] + bx, acc[mt][nt][1] + by);
            *(float2*)&C[(size_t)(m0 + 8) * ldc + n0] = make_float2(acc[mt][nt][2] + bx, acc[mt][nt][3] + by);
        }
}

// ================= pipelined flash attention =================
// grid (4, BH_), 256 threads; double-buffered K/V tiles, one syncthreads per j-tile.
#define KT_SZ   (64*68)
#define V_SZ    (64*72)
#define V1_BASE (2*KT_SZ)
#define V2_BASE (V1_BASE + 2*V_SZ)
#define PQ_OFF  (V2_BASE + 2*V_SZ)
#define FA_SMEM_WORDS (PQ_OFF + 128*68)

__global__ void __launch_bounds__(256, 1) flash_attn()
{
    const int bh = blockIdx.y;
    const int b = bh >> 3, h = bh & 7;
    const int i0 = blockIdx.x * 128;
    const float* Q  = g_qq + (size_t)bh * N_ * D_;
    const float* Kp = g_kk + (size_t)bh * N_ * D_;
    const float* Vv = g_vv + (size_t)bh * N_ * D_;
    const float* Vm = g_vm + (size_t)bh * N_ * D_;
    uint32_t* PQ = s_dyn + PQ_OFF;

    const int tid = threadIdx.x;
    const int lane = tid & 31, wid = tid >> 5;
    const int gr = lane >> 2, gc = lane & 3;
    const int rbase = wid * 16;
    const int lc4 = (tid & 15) * 4, lrr = tid >> 4;

    // ---- stage Q (coalesced) then pull frags to registers ----
    {
        float* Qst = (float*)PQ;
        #pragma unroll
        for (int e = 0; e < 8; e++) {
            int row = lrr + e * 16, gi = i0 + row;
            float4 q = make_float4(0.f,0.f,0.f,0.f);
            if (gi < N_) q = *(const float4*)(Q + (size_t)gi * D_ + lc4);
            *(float4*)&Qst[row * 68 + lc4] = q;
        }
    }
    __syncthreads();
    uint32_t qf[8][4];
    {
        const float* Qst = (const float*)PQ;
        #pragma unroll
        for (int kc = 0; kc < 8; kc++) {
            qf[kc][0] = to_tf32(Qst[(rbase + gr    ) * 68 + kc*8 + gc    ]);
            qf[kc][1] = to_tf32(Qst[(rbase + gr + 8) * 68 + kc*8 + gc    ]);
            qf[kc][2] = to_tf32(Qst[(rbase + gr    ) * 68 + kc*8 + gc + 4]);
            qf[kc][3] = to_tf32(Qst[(rbase + gr + 8) * 68 + kc*8 + gc + 4]);
        }
    }
    __syncthreads();

    float acc1[8][4], acc2[8][4];
    #pragma unroll
    for (int nt = 0; nt < 8; nt++)
        #pragma unroll
        for (int e = 0; e < 4; e++) { acc1[nt][e] = 0.f; acc2[nt][e] = 0.f; }
    float rmax0 = -1e30f, rmax1 = -1e30f, rsum0 = 0.f, rsum1 = 0.f;

    // ---- prefetch tile 0 ----
    float4 kvr[4], v1r[4], v2r[4];
    #pragma unroll
    for (int e = 0; e < 4; e++) {
        int j = lrr + e * 16;
        kvr[e] = make_float4(0.f,0.f,0.f,0.f); v1r[e] = kvr[e]; v2r[e] = kvr[e];
        if (j < N_) {
            kvr[e] = *(const float4*)(Kp + (size_t)j * D_ + lc4);
            v1r[e] = *(const float4*)(Vv + (size_t)j * D_ + lc4);
            v2r[e] = *(const float4*)(Vm + (size_t)j * D_ + lc4);
        }
    }

    const int ntiles = (N_ + 63) / 64;   // 8
    for (int t = 0; t < ntiles; t++) {
        const int j0 = t * 64;
        uint32_t* Kt = s_dyn + (t & 1) * KT_SZ;
        uint32_t* V1 = s_dyn + V1_BASE + (t & 1) * V_SZ;
        uint32_t* V2 = s_dyn + V2_BASE + (t & 1) * V_SZ;
        // store staged tile (cvt to tf32)
        #pragma unroll
        for (int e = 0; e < 4; e++) {
            int row = lrr + e * 16;
            *(uint4*)&Kt[row * 68 + lc4] = to_tf32_v4(kvr[e]);
            *(uint4*)&V1[row * 72 + lc4] = to_tf32_v4(v1r[e]);
            *(uint4*)&V2[row * 72 + lc4] = to_tf32_v4(v2r[e]);
        }
        // prefetch next tile
        if (t + 1 < ntiles) {
            int j0n = j0 + 64;
            #pragma unroll
            for (int e = 0; e < 4; e++) {
                int j = j0n + lrr + e * 16;
                kvr[e] = make_float4(0.f,0.f,0.f,0.f); v1r[e] = kvr[e]; v2r[e] = kvr[e];
                if (j < N_) {
                    kvr[e] = *(const float4*)(Kp + (size_t)j * D_ + lc4);
                    v1r[e] = *(const float4*)(Vv + (size_t)j * D_ + lc4);
                    v2r[e] = *(const float4*)(Vm + (size_t)j * D_ + lc4);
                }
            }
        }
        __syncthreads();

        // ---- S = Q @ K^T (m16 x n64 per warp) ----
        float sacc[8][4];
        #pragma unroll
        for (int nt = 0; nt < 8; nt++)
            #pragma unroll
            for (int e = 0; e < 4; e++) sacc[nt][e] = 0.f;
        #pragma unroll
        for (int nt = 0; nt < 8; nt++) {
            #pragma unroll
            for (int kc = 0; kc < 8; kc++) {
                uint32_t bf[2];
                bf[0] = Kt[(nt*8 + gr) * 68 + kc*8 + gc    ];
                bf[1] = Kt[(nt*8 + gr) * 68 + kc*8 + gc + 4];
                mma_tf32(sacc[nt], qf[kc], bf);
            }
        }
        // ---- mask tail columns ----
        if (j0 + 64 > N_) {
            #pragma unroll
            for (int nt = 0; nt < 8; nt++) {
                int cc = j0 + nt*8 + gc*2;
                if (cc     >= N_) { sacc[nt][0] = -1e30f; sacc[nt][2] = -1e30f; }
                if (cc + 1 >= N_) { sacc[nt][1] = -1e30f; sacc[nt][3] = -1e30f; }
            }
        }
        // ---- online softmax ----
        float tm0 = -1e30f, tm1 = -1e30f;
        #pragma unroll
        for (int nt = 0; nt < 8; nt++) {
            tm0 = fmaxf(tm0, fmaxf(sacc[nt][0], sacc[nt][1]));
            tm1 = fmaxf(tm1, fmaxf(sacc[nt][2], sacc[nt][3]));
        }
        tm0 = fmaxf(tm0, __shfl_xor_sync(0xffffffffu, tm0, 1));
        tm0 = fmaxf(tm0, __shfl_xor_sync(0xffffffffu, tm0, 2));
        tm1 = fmaxf(tm1, __shfl_xor_sync(0xffffffffu, tm1, 1));
        tm1 = fmaxf(tm1, __shfl_xor_sync(0xffffffffu, tm1, 2));
        float nm0 = fmaxf(rmax0, tm0), nm1 = fmaxf(rmax1, tm1);
        float sc0 = __expf(rmax0 - nm0), sc1 = __expf(rmax1 - nm1);
        rmax0 = nm0; rmax1 = nm1;
        float ps0 = 0.f, ps1 = 0.f;
        #pragma unroll
        for (int nt = 0; nt < 8; nt++) {
            float p00 = __expf(sacc[nt][0] - nm0);
            float p01 = __expf(sacc[nt][1] - nm0);
            float p10 = __expf(sacc[nt][2] - nm1);
            float p11 = __expf(sacc[nt][3] - nm1);
            ps0 += p00 + p01; ps1 += p10 + p11;
            *(uint2*)&PQ[(rbase + gr    ) * 68 + nt*8 + gc*2] = make_uint2(to_tf32(p00), to_tf32(p01));
            *(uint2*)&PQ[(rbase + gr + 8) * 68 + nt*8 + gc*2] = make_uint2(to_tf32(p10), to_tf32(p11));
            acc1[nt][0] *= sc0; acc1[nt][1] *= sc0; acc1[nt][2] *= sc1; acc1[nt][3] *= sc1;
            acc2[nt][0] *= sc0; acc2[nt][1] *= sc0; acc2[nt][2] *= sc1; acc2[nt][3] *= sc1;
        }
        ps0 += __shfl_xor_sync(0xffffffffu, ps0, 1);
        ps0 += __shfl_xor_sync(0xffffffffu, ps0, 2);
        ps1 += __shfl_xor_sync(0xffffffffu, ps1, 1);
        ps1 += __shfl_xor_sync(0xffffffffu, ps1, 2);
        rsum0 = rsum0 * sc0 + ps0;
        rsum1 = rsum1 * sc1 + ps1;
        __syncwarp();   // warp-private PQ rows visible

        // ---- PV: acc1 += P@V1, acc2 += P@V2 ----
        #pragma unroll
        for (int kc = 0; kc < 8; kc++) {
            uint32_t af[4];
            af[0] = PQ[(rbase + gr    ) * 68 + kc*8 + gc    ];
            af[1] = PQ[(rbase + gr + 8) * 68 + kc*8 + gc    ];
            af[2] = PQ[(rbase + gr    ) * 68 + kc*8 + gc + 4];
            af[3] = PQ[(rbase + gr + 8) * 68 + kc*8 + gc + 4];
            #pragma unroll
            for (int nt = 0; nt < 8; nt++) {
                uint32_t bv1[2], bv2[2];
                bv1[0] = V1[(kc*8 + gc    ) * 72 + nt*8 + gr];
                bv1[1] = V1[(kc*8 + gc + 4) * 72 + nt*8 + gr];
                bv2[0] = V2[(kc*8 + gc    ) * 72 + nt*8 + gr];
                bv2[1] = V2[(kc*8 + gc + 4) * 72 + nt*8 + gr];
                mma_tf32(acc1[nt], af, bv1);
                mma_tf32(acc2[nt], af, bv2);
            }
        }
    }

    // ---- epilogue ----
    float inv0 = 1.0f / rsum0, inv1 = 1.0f / rsum1;
    int gi0 = i0 + rbase + gr, gi1 = gi0 + 8;
    if (gi0 < N_) {
        float f = inv0 * g_upd[b * N_ + gi0];
        size_t base = (size_t)(b * N_ + gi0) * DIM_ + h * 64;
        #pragma unroll
        for (int nt = 0; nt < 8; nt++) {
            int d = nt*8 + gc*2;
            *(float2*)&g_out[base + d] = make_float2(acc1[nt][0]*f, acc1[nt][1]*f);
            *(float2*)&g_m  [base + d] = make_float2(acc2[nt][0]*f, acc2[nt][1]*f);
        }
    }
    if (gi1 < N_) {
        float f = inv1 * g_upd[b * N_ + gi1];
        size_t base = (size_t)(b * N_ + gi1) * DIM_ + h * 64;
        #pragma unroll
        for (int nt = 0; nt < 8; nt++) {
            int d = nt*8 + gc*2;
            *(float2*)&g_out[base + d] = make_float2(acc1[nt][2]*f, acc1[nt][3]*f);
            *(float2*)&g_m  [base + d] = make_float2(acc2[nt][2]*f, acc2[nt][3]*f);
        }
    }
}

// ---------------- updated[b,i] ----------------
__global__ void updated_k(const float* __restrict__ mask)
{
    int row = blockIdx.x * (blockDim.x >> 5) + (threadIdx.x >> 5);
    if (row >= BN_) return;
    int ln = threadIdx.x & 31;
    const float* p = mask + (size_t)row * DIM_;
    float s = 0.f;
    #pragma unroll
    for (int e = ln; e < DIM_; e += 32) s += p[e];
    #pragma unroll
    for (int o = 16; o > 0; o >>= 1) s += __shfl_xor_sync(0xffffffffu, s, o);
    if (ln == 0) {
        int i = row % N_;
        g_upd[row] = (i == 0) ? 1.0f : (s > 0.0f ? 1.0f : 0.0f);
    }
}

// ---------------- per-(b,h,w,d) max over sequence ----------------
__global__ void reduce_max_k()
{
    int o = blockIdx.x * blockDim.x + threadIdx.x;
    if (o >= B_*H_*3*D_) return;
    int d = o & 63;
    int w = (o >> 6) % 3;
    int h = ((o >> 6) / 3) % H_;
    int b = (o >> 6) / 24;
    const float* p = g_qkvm + (size_t)b * N_ * QKV_ + w * DIM_ + h * 64 + d;
    float mx = -1e30f;
    for (int i = 0; i < N_; i++) mx = fmaxf(mx, p[(size_t)i * QKV_]);
    g_max[o] = mx;
}

// ---------------- modulated q,k,v ----------------
__global__ void modulate_k()
{
    int idx = blockIdx.x * blockDim.x + threadIdx.x;
    if (idx >= SZ_BND) return;
    int hd = idx % DIM_;
    int i  = (idx / DIM_) % N_;
    int b  = idx / (DIM_ * N_);
    int h = hd >> 6, d = hd & 63;
    size_t base = (size_t)(b * N_ + i) * QKV_;
    float q  = g_qkv [base + hd];
    float k  = g_qkv [base + DIM_ + hd];
    float v  = g_qkv [base + 2*DIM_ + hd];
    float qm = g_qkvm[base + hd];
    float km = g_qkvm[base + DIM_ + hd];
    float vm = g_qkvm[base + 2*DIM_ + hd];
    int mb = ((b * H_ + h) * 3) * 64 + d;
    float qmn = qm / (1e-6f + g_max[mb]);
    float kmn = km / (1e-6f + g_max[mb + 64]);
    float vmn = vm / (1e-6f + g_max[mb + 128]);
    size_t o = ((size_t)(b * H_ + h) * N_ + i) * D_ + d;
    g_qq[o] = q * qmn * SCALE_;
    g_kk[o] = k * kmn;
    g_vv[o] = v * vmn;
    g_vm[o] = vmn;
}

// ---------------- overlap blending ----------------
__global__ void blend_k()
{
    int idx = blockIdx.x * blockDim.x + threadIdx.x;
    if (idx >= SZ_BND) return;
    int c = idx % DIM_;
    int i = (idx / DIM_) % N_;
    int b = idx / (DIM_ * N_);
    float o = g_out[idx], mv = g_m[idx];
    if (i >= 1 && i <= NHW_) {
        int p = i - 1, y = p >> 4, x = p & 15;
        float inv = 1.0f - g_upd[b * N_ + i];
        float s1 = 0.f, s2 = 0.f;
        #pragma unroll
        for (int dy = -1; dy <= 0; dy++)
            #pragma unroll
            for (int dx = -1; dx <= 0; dx++) {
                int r = y + dy, cc = x + dx;
                if (r >= 0 && r < 15 && cc >= 0 && cc < 15) {
                    size_t src = ((size_t)(b * N_ + TAIL0_ + r * 15 + cc)) * DIM_ + c;
                    s1 += g_out[src]; s2 += g_m[src];
                }
            }
        o  += 0.25f * s1 * inv;
        mv += 0.25f * s2 * inv;
    } else if (i >= TAIL0_) {
        int p = i - TAIL0_, r = p / 15, cc = p % 15;
        float inv = 1.0f - g_upd[b * N_ + i];
        float s1 = 0.f, s2 = 0.f;
        #pragma unroll
        for (int dy = 0; dy <= 1; dy++)
            #pragma unroll
            for (int dx = 0; dx <= 1; dx++) {
                size_t src = ((size_t)(b * N_ + 1 + (r + dy) * 16 + (cc + dx))) * DIM_ + c;
                s1 += g_out[src]; s2 += g_m[src];
            }
        o  += 0.25f * s1 * inv;
        mv += 0.25f * s2 * inv;
    }
    g_out2[idx] = o;
    g_m2[idx] = mv;
}

// ---------------- channel means ----------------
__global__ void mm_k()
{
    int row = blockIdx.x * (blockDim.x >> 5) + (threadIdx.x >> 5);
    if (row >= B_ * (N_ - 1)) return;
    int b = row / (N_ - 1), j = row % (N_ - 1);
    int ln = threadIdx.x & 31;
    const float* p = g_m2 + (size_t)(b * N_ + j + 1) * DIM_;
    float s = 0.f;
    #pragma unroll
    for (int e = ln; e < DIM_; e += 32) s += p[e];
    #pragma unroll
    for (int o = 16; o > 0; o >>= 1) s += __shfl_xor_sync(0xffffffffu, s, o);
    if (ln == 0) g_mm[row] = s * (1.0f / DIM_);
}

// ---------------- inter ----------------
__global__ void inter_k(float* __restrict__ outp)
{
    int idx = blockIdx.x * blockDim.x + threadIdx.x;
    if (idx >= B_ * 256 * 256) return;
    int x = idx & 255, y = (idx >> 8) & 255, b = idx >> 16;
    float v = g_mm[b * (N_ - 1) + (y >> 4) * 16 + (x >> 4)];
    if (y >= 8 && y < 248 && x >= 8 && x < 248) {
        float sh = g_mm[b * (N_ - 1) + 256 + ((y - 8) >> 4) * 15 + ((x - 8) >> 4)];
        v = 0.5f * (v + sh);
    }
    outp[idx] = v;
}

// ---------------- launch ----------------
extern "C" void kernel_launch(void* const* d_in, const int* in_sizes, int n_in,
                              void* d_out, int out_size)
{
    const float* x    = (const float*)d_in[0];
    const float* mask = (const float*)d_in[1];
    const float* Wqkv = (const float*)d_in[2];
    const float* Wout = (const float*)d_in[3];
    const float* bout = (const float*)d_in[4];
    float* out = (float*)d_out;

    float *p_qkv, *p_qkvm, *p_out2, *p_m2;
    cudaGetSymbolAddress((void**)&p_qkv,  g_qkv);
    cudaGetSymbolAddress((void**)&p_qkvm, g_qkvm);
    cudaGetSymbolAddress((void**)&p_out2, g_out2);
    cudaGetSymbolAddress((void**)&p_m2,   g_m2);

    const int gemm_smem = 2 * 2 * GEMM_BUF * 4;   // 73728 B
    cudaFuncSetAttribute(mma_gemm<false,false>, cudaFuncAttributeMaxDynamicSharedMemorySize, gemm_smem);
    cudaFuncSetAttribute(mma_gemm<true, false>, cudaFuncAttributeMaxDynamicSharedMemorySize, gemm_smem);
    cudaFuncSetAttribute(mma_gemm<false,true >, cudaFuncAttributeMaxDynamicSharedMemorySize, gemm_smem);
    cudaFuncSetAttribute(flash_attn, cudaFuncAttributeMaxDynamicSharedMemorySize, FA_SMEM_WORDS * 4);

    // 1-2. qkv = x @ Wqkv^T ; qkv_m = mask @ |Wqkv|^T   (tf32, pipelined)
    mma_gemm<false,false><<<dim3(QKV_/128, BN_/128), 256, gemm_smem>>>(x,    Wqkv, nullptr, p_qkv,  DIM_, DIM_, DIM_, QKV_);
    mma_gemm<true, false><<<dim3(QKV_/128, BN_/128), 256, gemm_smem>>>(mask, Wqkv, nullptr, p_qkvm, DIM_, DIM_, DIM_, QKV_);
    // 3. updated flags
    updated_k<<<(BN_ + 7) / 8, 256>>>(mask);
    // 4. maxima
    reduce_max_k<<<(B_*H_*3*D_ + 255) / 256, 256>>>();
    // 5. modulate
    modulate_k<<<(SZ_BND + 255) / 256, 256>>>();
    // 6-8. fused attention
    flash_attn<<<dim3(4, BH_), 256, FA_SMEM_WORDS * 4>>>();
    // 9. blending
    blend_k<<<(SZ_BND + 255) / 256, 256>>>();
    // 10. channel means
    mm_k<<<(B_ * (N_ - 1) + 7) / 8, 256>>>();
    // 11. inter
    inter_k<<<(B_ * 65536 + 255) / 256, 256>>>(out + 2 * (size_t)SZ_BND);
    // 12-13. final projections (tf32, pipelined) straight into d_out
    mma_gemm<false,true ><<<dim3(DIM_/128, BN_/128), 256, gemm_smem>>>(p_out2, Wout, bout,    out,                  DIM_, DIM_, DIM_, DIM_);
    mma_gemm<true, false><<<dim3(DIM_/128, BN_/128), 256, gemm_smem>>>(p_m2,   Wout, nullptr, out + (size_t)SZ_BND, DIM_, DIM_, DIM_, DIM_);
}

// round 9
// speedup vs baseline: 1.2521x; 1.2521x over previous
#include <cuda_runtime.h>
#include <cstdint>

// ---------------- problem constants ----------------
#define B_    64
#define N_    482
#define DIM_  512
#define H_    8
#define D_    64
#define QKV_  1536
#define BH_   (B_*H_)          // 512
#define BN_   (B_*N_)          // 30848
#define SZ_BND (BN_*DIM_)      // 15794176
#define NHW_  256
#define NB_   225
#define TAIL0_ 257
#define SCALE_ 0.125f

// RNA-to-tf32 via integer add: HMMA truncates low 13 bits in HW,
// so bits+0x1000 (round half up, carry propagates into exponent) == cvt.rna.tf32.
#define RNA_ 0x1000u

// ---------------- device scratch ----------------
__device__ float g_qkv [(size_t)BN_*QKV_];
__device__ float g_qkvm[(size_t)BN_*QKV_];
__device__ float g_qq  [(size_t)BH_*N_*D_];
__device__ float g_kk  [(size_t)BH_*N_*D_];
__device__ float g_vv  [(size_t)BH_*N_*D_];
__device__ float g_vm  [(size_t)BH_*N_*D_];
__device__ float g_out [SZ_BND];
__device__ float g_m   [SZ_BND];
__device__ float g_out2[SZ_BND];
__device__ float g_m2  [SZ_BND];
__device__ float g_max [B_*H_*3*D_];
__device__ float g_upd [BN_];
__device__ float g_mm  [B_*(N_-1)];

// ---------------- mma / async helpers ----------------
__device__ __forceinline__ void mma_tf32(float* c, const uint32_t* a, const uint32_t* b) {
    asm volatile("mma.sync.aligned.m16n8k8.row.col.f32.tf32.tf32.f32 "
        "{%0,%1,%2,%3}, {%4,%5,%6,%7}, {%8,%9}, {%0,%1,%2,%3};"
        : "+f"(c[0]), "+f"(c[1]), "+f"(c[2]), "+f"(c[3])
        : "r"(a[0]), "r"(a[1]), "r"(a[2]), "r"(a[3]), "r"(b[0]), "r"(b[1]));
}
__device__ __forceinline__ uint32_t smem_u32(const void* p) {
    return (uint32_t)__cvta_generic_to_shared(p);
}
__device__ __forceinline__ void cp16(uint32_t dst, const void* src, int sz) {
    asm volatile("cp.async.cg.shared.global [%0], [%1], 16, %2;" :: "r"(dst), "l"(src), "r"(sz));
}
#define CP_COMMIT() asm volatile("cp.async.commit_group;")
#define CP_WAIT(n)  asm volatile("cp.async.wait_group %0;" :: "n"(n))

extern __shared__ uint32_t s_dyn[];

// ================= cp.async-pipelined tf32 NT GEMM, 128x128 tile =================
// C[m,n] = sum_k A[m*lda+k] * f(B[n*ldb+k]) (+bias[n]); M,N mult of 128, K of 32.
// smem holds RAW f32; +RNA_ on fragment words restores round-to-nearest.
#define GEMM_BUF (128*36)
template<bool ABS_B, bool BIAS>
__global__ void __launch_bounds__(256) mma_gemm(const float* __restrict__ A,
                                                const float* __restrict__ Bm,
                                                const float* __restrict__ bias,
                                                float* __restrict__ C,
                                                int K, int lda, int ldb, int ldc)
{
    float* AsB = (float*)s_dyn;                   // [2][128*36]
    float* BsB = (float*)s_dyn + 2 * GEMM_BUF;    // [2][128*36]
    const int tid = threadIdx.x;
    const int bm = blockIdx.y * 128, bn = blockIdx.x * 128;
    const int lane = tid & 31, wid = tid >> 5;
    const int gr = lane >> 2, gc = lane & 3;
    const int wm = (wid & 1) * 64, wn = (wid >> 1) * 32;
    const int lr = tid >> 3, lc = (tid & 7) * 4;
    const float* Ap = A  + (size_t)(bm + lr) * lda + lc;
    const float* Bp = Bm + (size_t)(bn + lr) * ldb + lc;

    float acc[4][4][4];
    #pragma unroll
    for (int i = 0; i < 4; i++)
        #pragma unroll
        for (int j = 0; j < 4; j++)
            #pragma unroll
            for (int e = 0; e < 4; e++) acc[i][j][e] = 0.f;

    const int nslab = K >> 5;
    // prologue: stage slab 0
    {
        float* As = AsB; float* Bs = BsB;
        #pragma unroll
        for (int r = 0; r < 4; r++) {
            cp16(smem_u32(&As[(lr + r*32) * 36 + lc]), Ap + (size_t)(r*32) * lda, 16);
            cp16(smem_u32(&Bs[(lr + r*32) * 36 + lc]), Bp + (size_t)(r*32) * ldb, 16);
        }
        CP_COMMIT();
    }

    for (int s = 0; s < nslab; s++) {
        if (s + 1 < nslab) {
            float* As = AsB + ((s+1) & 1) * GEMM_BUF;
            float* Bs = BsB + ((s+1) & 1) * GEMM_BUF;
            int kt = (s + 1) * 32;
            #pragma unroll
            for (int r = 0; r < 4; r++) {
                cp16(smem_u32(&As[(lr + r*32) * 36 + lc]), Ap + (size_t)(r*32) * lda + kt, 16);
                cp16(smem_u32(&Bs[(lr + r*32) * 36 + lc]), Bp + (size_t)(r*32) * ldb + kt, 16);
            }
            CP_COMMIT();
            CP_WAIT(1);
        } else {
            CP_WAIT(0);
        }
        __syncthreads();

        const uint32_t* As = (const uint32_t*)(AsB + (s & 1) * GEMM_BUF);
        const uint32_t* Bs = (const uint32_t*)(BsB + (s & 1) * GEMM_BUF);
        #pragma unroll
        for (int ks = 0; ks < 4; ks++) {
            const int k0 = ks * 8;
            uint32_t ah[4][4], bh[4][2];
            #pragma unroll
            for (int mt = 0; mt < 4; mt++) {
                int r0 = wm + mt * 16 + gr;
                ah[mt][0] = As[(r0    ) * 36 + k0 + gc    ] + RNA_;
                ah[mt][1] = As[(r0 + 8) * 36 + k0 + gc    ] + RNA_;
                ah[mt][2] = As[(r0    ) * 36 + k0 + gc + 4] + RNA_;
                ah[mt][3] = As[(r0 + 8) * 36 + k0 + gc + 4] + RNA_;
            }
            #pragma unroll
            for (int nt = 0; nt < 4; nt++) {
                int c0 = wn + nt * 8 + gr;
                uint32_t b0 = Bs[c0 * 36 + k0 + gc    ];
                uint32_t b1 = Bs[c0 * 36 + k0 + gc + 4];
                if (ABS_B) { b0 &= 0x7fffffffu; b1 &= 0x7fffffffu; }
                bh[nt][0] = b0 + RNA_;
                bh[nt][1] = b1 + RNA_;
            }
            #pragma unroll
            for (int mt = 0; mt < 4; mt++)
                #pragma unroll
                for (int nt = 0; nt < 4; nt++)
                    mma_tf32(acc[mt][nt], ah[mt], bh[nt]);
        }
        __syncthreads();
    }
    #pragma unroll
    for (int mt = 0; mt < 4; mt++)
        #pragma unroll
        for (int nt = 0; nt < 4; nt++) {
            int m0 = bm + wm + mt * 16 + gr;
            int n0 = bn + wn + nt * 8 + gc * 2;
            float bx = 0.f, by = 0.f;
            if (BIAS) { bx = bias[n0]; by = bias[n0 + 1]; }
            *(float2*)&C[(size_t)m0 * ldc + n0] = make_float2(acc[mt][nt][0] + bx, acc[mt][nt][1] + by);
            *(float2*)&C[(size_t)(m0 + 8) * ldc + n0] = make_float2(acc[mt][nt][2] + bx, acc[mt][nt][3] + by);
        }
}

// ================= cp.async-pipelined flash attention =================
// grid (4, BH_), 256 threads; double-buffered K/V1/V2 tiles, raw f32 in smem, +RNA_ on frags.
#define KT_SZ   (64*68)
#define V_SZ    (64*72)
#define V1_BASE (2*KT_SZ)
#define V2_BASE (V1_BASE + 2*V_SZ)
#define PQ_OFF  (V2_BASE + 2*V_SZ)
#define FA_SMEM_WORDS (PQ_OFF + 128*68)

__global__ void __launch_bounds__(256, 1) flash_attn()
{
    const int bh = blockIdx.y;
    const int b = bh >> 3, h = bh & 7;
    const int i0 = blockIdx.x * 128;
    const float* Q  = g_qq + (size_t)bh * N_ * D_;
    const float* Kp = g_kk + (size_t)bh * N_ * D_;
    const float* Vv = g_vv + (size_t)bh * N_ * D_;
    const float* Vm = g_vm + (size_t)bh * N_ * D_;
    uint32_t* PQ = s_dyn + PQ_OFF;

    const int tid = threadIdx.x;
    const int lane = tid & 31, wid = tid >> 5;
    const int gr = lane >> 2, gc = lane & 3;
    const int rbase = wid * 16;
    const int lc4 = (tid & 15) * 4, lrr = tid >> 4;

    // ---- stage Q (coalesced, raw f32) then pull frags (RNA applied once) ----
    {
        float* Qst = (float*)PQ;
        #pragma unroll
        for (int e = 0; e < 8; e++) {
            int row = lrr + e * 16, gi = i0 + row;
            float4 q = make_float4(0.f,0.f,0.f,0.f);
            if (gi < N_) q = *(const float4*)(Q + (size_t)gi * D_ + lc4);
            *(float4*)&Qst[row * 68 + lc4] = q;
        }
    }
    __syncthreads();
    uint32_t qf[8][4];
    #pragma unroll
    for (int kc = 0; kc < 8; kc++) {
        qf[kc][0] = PQ[(rbase + gr    ) * 68 + kc*8 + gc    ] + RNA_;
        qf[kc][1] = PQ[(rbase + gr + 8) * 68 + kc*8 + gc    ] + RNA_;
        qf[kc][2] = PQ[(rbase + gr    ) * 68 + kc*8 + gc + 4] + RNA_;
        qf[kc][3] = PQ[(rbase + gr + 8) * 68 + kc*8 + gc + 4] + RNA_;
    }
    __syncthreads();

    float acc1[8][4], acc2[8][4];
    #pragma unroll
    for (int nt = 0; nt < 8; nt++)
        #pragma unroll
        for (int e = 0; e < 4; e++) { acc1[nt][e] = 0.f; acc2[nt][e] = 0.f; }
    float rmax0 = -1e30f, rmax1 = -1e30f, rsum0 = 0.f, rsum1 = 0.f;

    const int ntiles = (N_ + 63) / 64;   // 8
    // prologue: stage tile 0 via cp.async (zero-fill OOB rows)
    {
        uint32_t* Kt = s_dyn;
        uint32_t* V1 = s_dyn + V1_BASE;
        uint32_t* V2 = s_dyn + V2_BASE;
        #pragma unroll
        for (int e = 0; e < 4; e++) {
            int row = lrr + e * 16, j = row;
            int ok = (j < N_);
            size_t off = (size_t)(ok ? j : 0) * D_ + lc4;
            int sz = ok ? 16 : 0;
            cp16(smem_u32(&Kt[row * 68 + lc4]), Kp + off, sz);
            cp16(smem_u32(&V1[row * 72 + lc4]), Vv + off, sz);
            cp16(smem_u32(&V2[row * 72 + lc4]), Vm + off, sz);
        }
        CP_COMMIT();
    }

    for (int t = 0; t < ntiles; t++) {
        const int j0 = t * 64;
        if (t + 1 < ntiles) {
            uint32_t* Kt = s_dyn + ((t+1) & 1) * KT_SZ;
            uint32_t* V1 = s_dyn + V1_BASE + ((t+1) & 1) * V_SZ;
            uint32_t* V2 = s_dyn + V2_BASE + ((t+1) & 1) * V_SZ;
            int j0n = j0 + 64;
            #pragma unroll
            for (int e = 0; e < 4; e++) {
                int row = lrr + e * 16, j = j0n + row;
                int ok = (j < N_);
                size_t off = (size_t)(ok ? j : 0) * D_ + lc4;
                int sz = ok ? 16 : 0;
                cp16(smem_u32(&Kt[row * 68 + lc4]), Kp + off, sz);
                cp16(smem_u32(&V1[row * 72 + lc4]), Vv + off, sz);
                cp16(smem_u32(&V2[row * 72 + lc4]), Vm + off, sz);
            }
            CP_COMMIT();
            CP_WAIT(1);
        } else {
            CP_WAIT(0);
        }
        __syncthreads();

        const uint32_t* Kt = s_dyn + (t & 1) * KT_SZ;
        const uint32_t* V1 = s_dyn + V1_BASE + (t & 1) * V_SZ;
        const uint32_t* V2 = s_dyn + V2_BASE + (t & 1) * V_SZ;

        // ---- S = Q @ K^T ----
        float sacc[8][4];
        #pragma unroll
        for (int nt = 0; nt < 8; nt++)
            #pragma unroll
            for (int e = 0; e < 4; e++) sacc[nt][e] = 0.f;
        #pragma unroll
        for (int nt = 0; nt < 8; nt++) {
            #pragma unroll
            for (int kc = 0; kc < 8; kc++) {
                uint32_t bf[2];
                bf[0] = Kt[(nt*8 + gr) * 68 + kc*8 + gc    ] + RNA_;
                bf[1] = Kt[(nt*8 + gr) * 68 + kc*8 + gc + 4] + RNA_;
                mma_tf32(sacc[nt], qf[kc], bf);
            }
        }
        // ---- mask tail columns ----
        if (j0 + 64 > N_) {
            #pragma unroll
            for (int nt = 0; nt < 8; nt++) {
                int cc = j0 + nt*8 + gc*2;
                if (cc     >= N_) { sacc[nt][0] = -1e30f; sacc[nt][2] = -1e30f; }
                if (cc + 1 >= N_) { sacc[nt][1] = -1e30f; sacc[nt][3] = -1e30f; }
            }
        }
        // ---- online softmax ----
        float tm0 = -1e30f, tm1 = -1e30f;
        #pragma unroll
        for (int nt = 0; nt < 8; nt++) {
            tm0 = fmaxf(tm0, fmaxf(sacc[nt][0], sacc[nt][1]));
            tm1 = fmaxf(tm1, fmaxf(sacc[nt][2], sacc[nt][3]));
        }
        tm0 = fmaxf(tm0, __shfl_xor_sync(0xffffffffu, tm0, 1));
        tm0 = fmaxf(tm0, __shfl_xor_sync(0xffffffffu, tm0, 2));
        tm1 = fmaxf(tm1, __shfl_xor_sync(0xffffffffu, tm1, 1));
        tm1 = fmaxf(tm1, __shfl_xor_sync(0xffffffffu, tm1, 2));
        float nm0 = fmaxf(rmax0, tm0), nm1 = fmaxf(rmax1, tm1);
        float sc0 = __expf(rmax0 - nm0), sc1 = __expf(rmax1 - nm1);
        rmax0 = nm0; rmax1 = nm1;
        float ps0 = 0.f, ps1 = 0.f;
        #pragma unroll
        for (int nt = 0; nt < 8; nt++) {
            float p00 = __expf(sacc[nt][0] - nm0);
            float p01 = __expf(sacc[nt][1] - nm0);
            float p10 = __expf(sacc[nt][2] - nm1);
            float p11 = __expf(sacc[nt][3] - nm1);
            ps0 += p00 + p01; ps1 += p10 + p11;
            *(uint2*)&PQ[(rbase + gr    ) * 68 + nt*8 + gc*2] = make_uint2(__float_as_uint(p00), __float_as_uint(p01));
            *(uint2*)&PQ[(rbase + gr + 8) * 68 + nt*8 + gc*2] = make_uint2(__float_as_uint(p10), __float_as_uint(p11));
            acc1[nt][0] *= sc0; acc1[nt][1] *= sc0; acc1[nt][2] *= sc1; acc1[nt][3] *= sc1;
            acc2[nt][0] *= sc0; acc2[nt][1] *= sc0; acc2[nt][2] *= sc1; acc2[nt][3] *= sc1;
        }
        ps0 += __shfl_xor_sync(0xffffffffu, ps0, 1);
        ps0 += __shfl_xor_sync(0xffffffffu, ps0, 2);
        ps1 += __shfl_xor_sync(0xffffffffu, ps1, 1);
        ps1 += __shfl_xor_sync(0xffffffffu, ps1, 2);
        rsum0 = rsum0 * sc0 + ps0;
        rsum1 = rsum1 * sc1 + ps1;
        __syncwarp();   // warp-private PQ rows visible

        // ---- PV: acc1 += P@V1, acc2 += P@V2 ----
        #pragma unroll
        for (int kc = 0; kc < 8; kc++) {
            uint32_t af[4];
            af[0] = PQ[(rbase + gr    ) * 68 + kc*8 + gc    ] + RNA_;
            af[1] = PQ[(rbase + gr + 8) * 68 + kc*8 + gc    ] + RNA_;
            af[2] = PQ[(rbase + gr    ) * 68 + kc*8 + gc + 4] + RNA_;
            af[3] = PQ[(rbase + gr + 8) * 68 + kc*8 + gc + 4] + RNA_;
            #pragma unroll
            for (int nt = 0; nt < 8; nt++) {
                uint32_t bv1[2], bv2[2];
                bv1[0] = V1[(kc*8 + gc    ) * 72 + nt*8 + gr] + RNA_;
                bv1[1] = V1[(kc*8 + gc + 4) * 72 + nt*8 + gr] + RNA_;
                bv2[0] = V2[(kc*8 + gc    ) * 72 + nt*8 + gr] + RNA_;
                bv2[1] = V2[(kc*8 + gc + 4) * 72 + nt*8 + gr] + RNA_;
                mma_tf32(acc1[nt], af, bv1);
                mma_tf32(acc2[nt], af, bv2);
            }
        }
        __syncthreads();   // all warps done reading this buffer before next issue overwrites
    }

    // ---- epilogue ----
    float inv0 = 1.0f / rsum0, inv1 = 1.0f / rsum1;
    int gi0 = i0 + rbase + gr, gi1 = gi0 + 8;
    if (gi0 < N_) {
        float f = inv0 * g_upd[b * N_ + gi0];
        size_t base = (size_t)(b * N_ + gi0) * DIM_ + h * 64;
        #pragma unroll
        for (int nt = 0; nt < 8; nt++) {
            int d = nt*8 + gc*2;
            *(float2*)&g_out[base + d] = make_float2(acc1[nt][0]*f, acc1[nt][1]*f);
            *(float2*)&g_m  [base + d] = make_float2(acc2[nt][0]*f, acc2[nt][1]*f);
        }
    }
    if (gi1 < N_) {
        float f = inv1 * g_upd[b * N_ + gi1];
        size_t base = (size_t)(b * N_ + gi1) * DIM_ + h * 64;
        #pragma unroll
        for (int nt = 0; nt < 8; nt++) {
            int d = nt*8 + gc*2;
            *(float2*)&g_out[base + d] = make_float2(acc1[nt][2]*f, acc1[nt][3]*f);
            *(float2*)&g_m  [base + d] = make_float2(acc2[nt][2]*f, acc2[nt][3]*f);
        }
    }
}

// ---------------- updated[b,i] ----------------
__global__ void updated_k(const float* __restrict__ mask)
{
    int row = blockIdx.x * (blockDim.x >> 5) + (threadIdx.x >> 5);
    if (row >= BN_) return;
    int ln = threadIdx.x & 31;
    const float* p = mask + (size_t)row * DIM_;
    float s = 0.f;
    #pragma unroll
    for (int e = ln; e < DIM_; e += 32) s += p[e];
    #pragma unroll
    for (int o = 16; o > 0; o >>= 1) s += __shfl_xor_sync(0xffffffffu, s, o);
    if (ln == 0) {
        int i = row % N_;
        g_upd[row] = (i == 0) ? 1.0f : (s > 0.0f ? 1.0f : 0.0f);
    }
}

// ---------------- per-(b,h,w,d) max over sequence ----------------
__global__ void reduce_max_k()
{
    int o = blockIdx.x * blockDim.x + threadIdx.x;
    if (o >= B_*H_*3*D_) return;
    int d = o & 63;
    int w = (o >> 6) % 3;
    int h = ((o >> 6) / 3) % H_;
    int b = (o >> 6) / 24;
    const float* p = g_qkvm + (size_t)b * N_ * QKV_ + w * DIM_ + h * 64 + d;
    float mx = -1e30f;
    for (int i = 0; i < N_; i++) mx = fmaxf(mx, p[(size_t)i * QKV_]);
    g_max[o] = mx;
}

// ---------------- modulated q,k,v ----------------
__global__ void modulate_k()
{
    int idx = blockIdx.x * blockDim.x + threadIdx.x;
    if (idx >= SZ_BND) return;
    int hd = idx % DIM_;
    int i  = (idx / DIM_) % N_;
    int b  = idx / (DIM_ * N_);
    int h = hd >> 6, d = hd & 63;
    size_t base = (size_t)(b * N_ + i) * QKV_;
    float q  = g_qkv [base + hd];
    float k  = g_qkv [base + DIM_ + hd];
    float v  = g_qkv [base + 2*DIM_ + hd];
    float qm = g_qkvm[base + hd];
    float km = g_qkvm[base + DIM_ + hd];
    float vm = g_qkvm[base + 2*DIM_ + hd];
    int mb = ((b * H_ + h) * 3) * 64 + d;
    float qmn = qm / (1e-6f + g_max[mb]);
    float kmn = km / (1e-6f + g_max[mb + 64]);
    float vmn = vm / (1e-6f + g_max[mb + 128]);
    size_t o = ((size_t)(b * H_ + h) * N_ + i) * D_ + d;
    g_qq[o] = q * qmn * SCALE_;
    g_kk[o] = k * kmn;
    g_vv[o] = v * vmn;
    g_vm[o] = vmn;
}

// ---------------- overlap blending ----------------
__global__ void blend_k()
{
    int idx = blockIdx.x * blockDim.x + threadIdx.x;
    if (idx >= SZ_BND) return;
    int c = idx % DIM_;
    int i = (idx / DIM_) % N_;
    int b = idx / (DIM_ * N_);
    float o = g_out[idx], mv = g_m[idx];
    if (i >= 1 && i <= NHW_) {
        int p = i - 1, y = p >> 4, x = p & 15;
        float inv = 1.0f - g_upd[b * N_ + i];
        float s1 = 0.f, s2 = 0.f;
        #pragma unroll
        for (int dy = -1; dy <= 0; dy++)
            #pragma unroll
            for (int dx = -1; dx <= 0; dx++) {
                int r = y + dy, cc = x + dx;
                if (r >= 0 && r < 15 && cc >= 0 && cc < 15) {
                    size_t src = ((size_t)(b * N_ + TAIL0_ + r * 15 + cc)) * DIM_ + c;
                    s1 += g_out[src]; s2 += g_m[src];
                }
            }
        o  += 0.25f * s1 * inv;
        mv += 0.25f * s2 * inv;
    } else if (i >= TAIL0_) {
        int p = i - TAIL0_, r = p / 15, cc = p % 15;
        float inv = 1.0f - g_upd[b * N_ + i];
        float s1 = 0.f, s2 = 0.f;
        #pragma unroll
        for (int dy = 0; dy <= 1; dy++)
            #pragma unroll
            for (int dx = 0; dx <= 1; dx++) {
                size_t src = ((size_t)(b * N_ + 1 + (r + dy) * 16 + (cc + dx))) * DIM_ + c;
                s1 += g_out[src]; s2 += g_m[src];
            }
        o  += 0.25f * s1 * inv;
        mv += 0.25f * s2 * inv;
    }
    g_out2[idx] = o;
    g_m2[idx] = mv;
}

// ---------------- channel means ----------------
__global__ void mm_k()
{
    int row = blockIdx.x * (blockDim.x >> 5) + (threadIdx.x >> 5);
    if (row >= B_ * (N_ - 1)) return;
    int b = row / (N_ - 1), j = row % (N_ - 1);
    int ln = threadIdx.x & 31;
    const float* p = g_m2 + (size_t)(b * N_ + j + 1) * DIM_;
    float s = 0.f;
    #pragma unroll
    for (int e = ln; e < DIM_; e += 32) s += p[e];
    #pragma unroll
    for (int o = 16; o > 0; o >>= 1) s += __shfl_xor_sync(0xffffffffu, s, o);
    if (ln == 0) g_mm[row] = s * (1.0f / DIM_);
}

// ---------------- inter ----------------
__global__ void inter_k(float* __restrict__ outp)
{
    int idx = blockIdx.x * blockDim.x + threadIdx.x;
    if (idx >= B_ * 256 * 256) return;
    int x = idx & 255, y = (idx >> 8) & 255, b = idx >> 16;
    float v = g_mm[b * (N_ - 1) + (y >> 4) * 16 + (x >> 4)];
    if (y >= 8 && y < 248 && x >= 8 && x < 248) {
        float sh = g_mm[b * (N_ - 1) + 256 + ((y - 8) >> 4) * 15 + ((x - 8) >> 4)];
        v = 0.5f * (v + sh);
    }
    outp[idx] = v;
}

// ---------------- launch ----------------
extern "C" void kernel_launch(void* const* d_in, const int* in_sizes, int n_in,
                              void* d_out, int out_size)
{
    const float* x    = (const float*)d_in[0];
    const float* mask = (const float*)d_in[1];
    const float* Wqkv = (const float*)d_in[2];
    const float* Wout = (const float*)d_in[3];
    const float* bout = (const float*)d_in[4];
    float* out = (float*)d_out;

    float *p_qkv, *p_qkvm, *p_out2, *p_m2;
    cudaGetSymbolAddress((void**)&p_qkv,  g_qkv);
    cudaGetSymbolAddress((void**)&p_qkvm, g_qkvm);
    cudaGetSymbolAddress((void**)&p_out2, g_out2);
    cudaGetSymbolAddress((void**)&p_m2,   g_m2);

    const int gemm_smem = 2 * 2 * GEMM_BUF * 4;   // 73728 B
    cudaFuncSetAttribute(mma_gemm<false,false>, cudaFuncAttributeMaxDynamicSharedMemorySize, gemm_smem);
    cudaFuncSetAttribute(mma_gemm<true, false>, cudaFuncAttributeMaxDynamicSharedMemorySize, gemm_smem);
    cudaFuncSetAttribute(mma_gemm<false,true >, cudaFuncAttributeMaxDynamicSharedMemorySize, gemm_smem);
    cudaFuncSetAttribute(flash_attn, cudaFuncAttributeMaxDynamicSharedMemorySize, FA_SMEM_WORDS * 4);

    // 1-2. qkv = x @ Wqkv^T ; qkv_m = mask @ |Wqkv|^T   (tf32, cp.async pipelined, RNA)
    mma_gemm<false,false><<<dim3(QKV_/128, BN_/128), 256, gemm_smem>>>(x,    Wqkv, nullptr, p_qkv,  DIM_, DIM_, DIM_, QKV_);
    mma_gemm<true, false><<<dim3(QKV_/128, BN_/128), 256, gemm_smem>>>(mask, Wqkv, nullptr, p_qkvm, DIM_, DIM_, DIM_, QKV_);
    // 3. updated flags
    updated_k<<<(BN_ + 7) / 8, 256>>>(mask);
    // 4. maxima
    reduce_max_k<<<(B_*H_*3*D_ + 255) / 256, 256>>>();
    // 5. modulate
    modulate_k<<<(SZ_BND + 255) / 256, 256>>>();
    // 6-8. fused attention
    flash_attn<<<dim3(4, BH_), 256, FA_SMEM_WORDS * 4>>>();
    // 9. blending
    blend_k<<<(SZ_BND + 255) / 256, 256>>>();
    // 10. channel means
    mm_k<<<(B_ * (N_ - 1) + 7) / 8, 256>>>();
    // 11. inter
    inter_k<<<(B_ * 65536 + 255) / 256, 256>>>(out + 2 * (size_t)SZ_BND);
    // 12-13. final projections
    mma_gemm<false,true ><<<dim3(DIM_/128, BN_/128), 256, gemm_smem>>>(p_out2, Wout, bout,    out,                  DIM_, DIM_, DIM_, DIM_);
    mma_gemm<true, false><<<dim3(DIM_/128, BN_/128), 256, gemm_smem>>>(p_m2,   Wout, nullptr, out + (size_t)SZ_BND, DIM_, DIM_, DIM_, DIM_);
}